// round 3
// baseline (speedup 1.0000x reference)
#include <cuda_runtime.h>
#include <math.h>

#define NL 51      // labels
#define NC 16      // channels
#define PC 17      // padded columns (16 sums + count / mn), kills smem bank conflicts
#define GRID1 1184 // 8 CTAs per SM on 148 SMs
#define BLK 256

static const long long CH_STRIDE = 1LL << 21;        // 32*256*256 = 2097152 floats per channel
static const long long NVOX = 2LL << 21;             // 2 * 2097152 = 4194304 voxels
static const int N4 = (int)(NVOX / 4);               // 1048576 voxel quads

// Scratch (allocation-free rule: __device__ globals)
static __device__ float  g_part1[GRID1][NL][PC];     // per-CTA sums(0..15) + count(16)
static __device__ float  g_part2[GRID1][NL];         // per-CTA intra-cos partials
static __device__ float  g_red[NL][PC];              // reduced sums + counts
static __device__ float  g_meanm[NL][PC];            // means(0..15) + mean-norm(16)
static __device__ double g_inter;                    // clipped inter-similarity mean

__device__ __forceinline__ double blockReduceD(double v) {
    __shared__ double sh[32];
    int lane = threadIdx.x & 31, w = threadIdx.x >> 5;
    #pragma unroll
    for (int o = 16; o; o >>= 1) v += __shfl_down_sync(0xffffffffu, v, o);
    if (lane == 0) sh[w] = v;
    __syncthreads();
    int nw = (blockDim.x + 31) >> 5;
    v = (threadIdx.x < nw) ? sh[threadIdx.x] : 0.0;
    if (w == 0) {
        #pragma unroll
        for (int o = 16; o; o >>= 1) v += __shfl_down_sync(0xffffffffu, v, o);
    }
    return v; // valid on thread 0
}

// ---------------- Pass 1: per-label counts + channel sums ----------------
__global__ void __launch_bounds__(BLK) k_pass1(const float* __restrict__ pred,
                                               const int* __restrict__ gt) {
    __shared__ float s[NL * PC];
    for (int i = threadIdx.x; i < NL * PC; i += BLK) s[i] = 0.f;
    __syncthreads();

    int g = blockIdx.x * BLK + threadIdx.x;
    for (int i4 = g; i4 < N4; i4 += GRID1 * BLK) {
        int4 lv = ((const int4*)gt)[i4];
        int l0 = lv.x * PC, l1 = lv.y * PC, l2 = lv.z * PC, l3 = lv.w * PC;
        atomicAdd(&s[l0 + 16], 1.f);
        atomicAdd(&s[l1 + 16], 1.f);
        atomicAdd(&s[l2 + 16], 1.f);
        atomicAdd(&s[l3 + 16], 1.f);

        size_t v0 = (size_t)i4 * 4;
        size_t b = v0 >> 21;
        size_t rest = v0 & (size_t)(CH_STRIDE - 1);
        const float4* base = (const float4*)(pred + b * (NC * (size_t)CH_STRIDE) + rest);
        #pragma unroll
        for (int k = 0; k < NC; k++) {
            float4 p = base[(size_t)k * (CH_STRIDE / 4)];
            atomicAdd(&s[l0 + k], p.x);
            atomicAdd(&s[l1 + k], p.y);
            atomicAdd(&s[l2 + k], p.z);
            atomicAdd(&s[l3 + k], p.w);
        }
    }
    __syncthreads();
    float* dst = &g_part1[blockIdx.x][0][0];
    for (int i = threadIdx.x; i < NL * PC; i += BLK) dst[i] = s[i];
}

// ---------------- Reduce partials (double accumulation) ----------------
__global__ void k_reduce1() { // grid NL*PC, block 128
    int l = blockIdx.x / PC, v = blockIdx.x % PC;
    double acc = 0.0;
    for (int c = threadIdx.x; c < GRID1; c += 128) acc += (double)g_part1[c][l][v];
    acc = blockReduceD(acc);
    if (threadIdx.x == 0) g_red[l][v] = (float)acc;
}

// ---------------- Stats: means, norms, inter-similarity ----------------
__global__ void k_stats() {
    __shared__ float s_cmn[NL - 1][NC];
    int t = threadIdx.x;
    if (t < NL) {
        float cnt = g_red[t][16];
        float cf = fmaxf(cnt, 1.f);
        float m[NC];
        float nrm2 = 0.f;
        #pragma unroll
        for (int k = 0; k < NC; k++) {
            m[k] = g_red[t][k] / cf;
            nrm2 += m[k] * m[k];
        }
        float mn = sqrtf(nrm2);
        #pragma unroll
        for (int k = 0; k < NC; k++) g_meanm[t][k] = m[k];
        g_meanm[t][16] = mn;
        if (t >= 1) {
            float inv = 1.f / fmaxf(mn, 1e-8f);
            #pragma unroll
            for (int k = 0; k < NC; k++) s_cmn[t - 1][k] = m[k] * inv;
        }
    }
    __syncthreads();

    // 50x50 upper triangle: 1225 pairs
    double acc = 0.0;
    for (int p = t; p < 1225; p += blockDim.x) {
        int i = 0, rem = p;
        while (rem >= (NL - 2) - i) { rem -= (NL - 2) - i; i++; }
        int j = i + 1 + rem;
        float d = 0.f;
        #pragma unroll
        for (int k = 0; k < NC; k++) d += s_cmn[i][k] * s_cmn[j][k];
        d = fminf(fmaxf(d, 0.f), 1.f);
        acc += (double)d;
    }
    acc = blockReduceD(acc);
    if (t == 0) g_inter = acc / 1225.0;
}

// ---------------- Pass 2: per-voxel cosine vs label mean ----------------
__global__ void __launch_bounds__(BLK) k_pass2(const float* __restrict__ pred,
                                               const int* __restrict__ gt) {
    __shared__ float sm[NL * PC]; // means + mn, padded
    __shared__ float si[NL];
    for (int i = threadIdx.x; i < NL * PC; i += BLK) sm[i] = (&g_meanm[0][0])[i];
    for (int i = threadIdx.x; i < NL; i += BLK) si[i] = 0.f;
    __syncthreads();

    int g = blockIdx.x * BLK + threadIdx.x;
    for (int i4 = g; i4 < N4; i4 += GRID1 * BLK) {
        int4 lv = ((const int4*)gt)[i4];
        int r0 = lv.x, r1 = lv.y, r2 = lv.z, r3 = lv.w;
        int l0 = r0 * PC, l1 = r1 * PC, l2 = r2 * PC, l3 = r3 * PC;

        size_t v0 = (size_t)i4 * 4;
        size_t b = v0 >> 21;
        size_t rest = v0 & (size_t)(CH_STRIDE - 1);
        const float4* base = (const float4*)(pred + b * (NC * (size_t)CH_STRIDE) + rest);

        float d0 = 0.f, d1 = 0.f, d2 = 0.f, d3 = 0.f;
        float q0 = 0.f, q1 = 0.f, q2 = 0.f, q3 = 0.f;
        #pragma unroll
        for (int k = 0; k < NC; k++) {
            float4 p = base[(size_t)k * (CH_STRIDE / 4)];
            d0 += p.x * sm[l0 + k]; q0 += p.x * p.x;
            d1 += p.y * sm[l1 + k]; q1 += p.y * p.y;
            d2 += p.z * sm[l2 + k]; q2 += p.z * p.z;
            d3 += p.w * sm[l3 + k]; q3 += p.w * p.w;
        }
        float c0 = __fdividef(d0, fmaxf(sqrtf(q0) * sm[l0 + 16], 1e-8f));
        float c1 = __fdividef(d1, fmaxf(sqrtf(q1) * sm[l1 + 16], 1e-8f));
        float c2 = __fdividef(d2, fmaxf(sqrtf(q2) * sm[l2 + 16], 1e-8f));
        float c3 = __fdividef(d3, fmaxf(sqrtf(q3) * sm[l3 + 16], 1e-8f));
        atomicAdd(&si[r0], c0);
        atomicAdd(&si[r1], c1);
        atomicAdd(&si[r2], c2);
        atomicAdd(&si[r3], c3);
    }
    __syncthreads();
    for (int i = threadIdx.x; i < NL; i += BLK) g_part2[blockIdx.x][i] = si[i];
}

// ---------------- Final: intra mean + loss ----------------
__global__ void k_final(float* __restrict__ out) {
    __shared__ float s_inv[NL];
    int t = threadIdx.x;
    if (t < NL) s_inv[t] = 1.f / fmaxf(g_red[t][16], 1.f);
    __syncthreads();

    double acc = 0.0;
    for (int idx = t; idx < (NL - 1) * GRID1; idx += blockDim.x) {
        int l = idx % (NL - 1) + 1;
        int c = idx / (NL - 1);
        acc += (double)g_part2[c][l] * (double)s_inv[l];
    }
    acc = blockReduceD(acc);
    if (t == 0) out[0] = (float)(g_inter - acc / (double)(NL - 1));
}

extern "C" void kernel_launch(void* const* d_in, const int* in_sizes, int n_in,
                              void* d_out, int out_size) {
    const float* pred = (const float*)d_in[0];
    const int* gt = (const int*)d_in[1];
    float* out = (float*)d_out;

    k_pass1<<<GRID1, BLK>>>(pred, gt);
    k_reduce1<<<NL * PC, 128>>>();
    k_stats<<<1, 256>>>();
    k_pass2<<<GRID1, BLK>>>(pred, gt);
    k_final<<<1, 256>>>(out);
}